// round 8
// baseline (speedup 1.0000x reference)
#include <cuda_runtime.h>
#include <cuda_bf16.h>
#include <cstdint>

#define NROWS 262144
#define CIN   256
#define MID   64
#define KOFF  9
#define EPS   1e-5f

// Pre-split bf16 tables for h2 (device globals; no allocs allowed).
__device__ unsigned short g_h2hi[(size_t)NROWS * MID];
__device__ unsigned short g_h2lo[(size_t)NROWS * MID];
__device__ int g_mask_mode;

// Pre-split, pre-transposed weight tiles in exact smem image:
// per tile 18432 B = [hi: 64n x 144B][lo: 64n x 144B] (pad bytes unused).
__device__ uint4 g_w1t[4 * 1152];
__device__ uint4 g_w2t[9 * 1152];
__device__ uint4 g_w3t[4 * 1152];

__device__ __forceinline__ uint32_t smem_to_u32(const void* p) {
    uint32_t a;
    asm("{ .reg .u64 t; cvta.to.shared.u64 t, %1; cvt.u32.u64 %0, t; }"
        : "=r"(a) : "l"(p));
    return a;
}

#define LDSM4(r, a)                                                            \
    asm volatile("ldmatrix.sync.aligned.m8n8.x4.shared.b16 {%0,%1,%2,%3}, [%4];" \
        : "=r"((r)[0]), "=r"((r)[1]), "=r"((r)[2]), "=r"((r)[3]) : "r"(a))

#define MMA_BF16(d, a, b)                                                      \
    asm volatile("mma.sync.aligned.m16n8k16.row.col.f32.bf16.bf16.f32 "        \
        "{%0,%1,%2,%3}, {%4,%5,%6,%7}, {%8,%9}, {%0,%1,%2,%3};"                \
        : "+f"((d)[0]), "+f"((d)[1]), "+f"((d)[2]), "+f"((d)[3])               \
        : "r"((a)[0]), "r"((a)[1]), "r"((a)[2]), "r"((a)[3]),                  \
          "r"((b)[0]), "r"((b)[1]))

#define CP_ASYNC16(dst, src, sz)                                               \
    asm volatile("cp.async.cg.shared.global [%0], [%1], 16, %2;"               \
                 :: "r"(dst), "l"(src), "r"(sz))
#define CP_COMMIT() asm volatile("cp.async.commit_group;" ::: "memory")
#define CP_WAIT1()  asm volatile("cp.async.wait_group 1;" ::: "memory")
#define CP_WAIT0()  asm volatile("cp.async.wait_group 0;" ::: "memory")

__device__ __forceinline__ void split2(float v0, float v1, uint32_t& hi, uint32_t& lo) {
    __nv_bfloat16 h0 = __float2bfloat16(v0), h1 = __float2bfloat16(v1);
    __nv_bfloat16 l0 = __float2bfloat16(v0 - __bfloat162float(h0));
    __nv_bfloat16 l1 = __float2bfloat16(v1 - __bfloat162float(h1));
    hi = (uint32_t)__bfloat16_as_ushort(h0) | ((uint32_t)__bfloat16_as_ushort(h1) << 16);
    lo = (uint32_t)__bfloat16_as_ushort(l0) | ((uint32_t)__bfloat16_as_ushort(l1) << 16);
}
__device__ __forceinline__ void split1(float v, unsigned short& h, unsigned short& l) {
    __nv_bfloat16 hb = __float2bfloat16(v);
    __nv_bfloat16 lb = __float2bfloat16(v - __bfloat162float(hb));
    h = __bfloat16_as_ushort(hb); l = __bfloat16_as_ushort(lb);
}

__device__ __forceinline__ bool mask_on(const void* p, size_t i, int mode) {
    switch (mode) {
        case 1:  return ((const unsigned char*)p)[i] != 0;
        case 2:  return ((const float*)p)[i] != 0.0f;
        case 3:  return ((const unsigned short*)p)[i] != 0;
        default: return ((const int*)p)[i] != 0;
    }
}

#define ASTRIDE 144

// ---------------------------------------------------------------------------
// kPrep: split+transpose all 17 weight tiles once. 1 CTA per tile.
// ---------------------------------------------------------------------------
__global__ void __launch_bounds__(256)
kPrep(const float* __restrict__ w1, const float* __restrict__ w2,
      const float* __restrict__ w3)
{
    const int bid = blockIdx.x, tid = threadIdx.x;
    const float* src; int ldw; unsigned char* d8;
    if (bid < 4)       { src = w1 + (size_t)bid * 64 * MID;    ldw = MID;
                         d8 = (unsigned char*)(g_w1t + bid * 1152); }
    else if (bid < 13) { src = w2 + (size_t)(bid - 4) * 4096;  ldw = MID;
                         d8 = (unsigned char*)(g_w2t + (bid - 4) * 1152); }
    else               { src = w3 + (bid - 13) * 64;           ldw = CIN;
                         d8 = (unsigned char*)(g_w3t + (bid - 13) * 1152); }
    const int kr = tid >> 2, ns = (tid & 3) * 16;
    const float4* wr = reinterpret_cast<const float4*>(src + (size_t)kr * ldw + ns);
    #pragma unroll
    for (int q = 0; q < 4; q++) {
        float4 v = wr[q];
        float e[4] = {v.x, v.y, v.z, v.w};
        #pragma unroll
        for (int j = 0; j < 4; j++) {
            int n = ns + q * 4 + j;
            unsigned short h, l; split1(e[j], h, l);
            *(unsigned short*)(d8 + n * ASTRIDE + kr * 2)        = h;
            *(unsigned short*)(d8 + 9216 + n * ASTRIDE + kr * 2) = l;
        }
    }
}

// Async copy of one 18432-B prepped tile (hi+lo) into smem.
__device__ __forceinline__ void copy_tile_async(uint32_t dst, const uint4* src, int tid) {
    #pragma unroll
    for (int i = 0; i < 4; i++)
        CP_ASYNC16(dst + (tid + i * 256) * 16, (const char*)(src + tid + i * 256), 16);
    if (tid < 128)
        CP_ASYNC16(dst + (tid + 1024) * 16, (const char*)(src + tid + 1024), 16);
}

// Warp tile 16x64, 3-MMA hi/lo scheme over one 64-deep K chunk.
__device__ __forceinline__ void gemm_chunk16(uint32_t sb, uint32_t ahi, uint32_t alo,
                                             uint32_t bhi, uint32_t blo,
                                             uint32_t aoff, uint32_t boff,
                                             float acc[8][4]) {
    #pragma unroll
    for (int ks = 0; ks < 4; ks++) {
        uint32_t ah[4], al[4];
        LDSM4(ah, sb + ahi + aoff + ks * 32);
        LDSM4(al, sb + alo + aoff + ks * 32);
        uint32_t bh[16], bl[16];
        #pragma unroll
        for (int p = 0; p < 4; p++) {
            LDSM4(bh + 4 * p, sb + bhi + boff + p * (16 * ASTRIDE) + ks * 32);
            LDSM4(bl + 4 * p, sb + blo + boff + p * (16 * ASTRIDE) + ks * 32);
        }
        #pragma unroll
        for (int nt = 0; nt < 8; nt++) {
            const uint32_t* fh = bh + (nt >> 1) * 4 + (nt & 1) * 2;
            const uint32_t* fl = bl + (nt >> 1) * 4 + (nt & 1) * 2;
            MMA_BF16(acc[nt], ah, fh);
            MMA_BF16(acc[nt], ah, fl);
            MMA_BF16(acc[nt], al, fh);
        }
    }
}

__device__ __forceinline__ uint32_t a_off(int wr0, int lane) {
    int row = wr0 + (lane & 7) + ((lane >> 3) & 1) * 8;
    return row * ASTRIDE + (lane >> 4) * 16;
}
__device__ __forceinline__ uint32_t b_off(int lane) {
    int n = (lane & 7) + (lane >> 4) * 8;
    return n * ASTRIDE + ((lane >> 3) & 1) * 16;
}

// ---------------------------------------------------------------------------
// Kernel A: h2 = relu(bn2( relu(bn1(x)) @ w1 + b1 )). BM=128.
// x prefetched to regs; B tiles double-buffered via cp.async from g_w1t.
// Last block (blockIdx.x == NROWS/128) runs the mask-dtype probe instead.
// ---------------------------------------------------------------------------
#define A_AHI  0
#define A_ALO  18432
#define A_B0   36864   /* hi 36864, lo 46080 */
#define A_B1   55296   /* hi 55296, lo 64512 */
#define A_PAR  73728

__global__ void __launch_bounds__(256)
kA(const float* __restrict__ x,
   const float* __restrict__ g1, const float* __restrict__ be1,
   const float* __restrict__ mu1, const float* __restrict__ va1,
   const float* __restrict__ b1,
   const float* __restrict__ g2, const float* __restrict__ be2,
   const float* __restrict__ mu2, const float* __restrict__ va2,
   const unsigned char* __restrict__ msk)
{
    const int tid = threadIdx.x;

    // ---- detection block ----
    if (blockIdx.x == NROWS / 128) {
        __shared__ int flags[3];
        if (tid < 3) flags[tid] = 0;
        __syncthreads();
        int f0 = 0, f1 = 0, f2 = 0;
        #pragma unroll
        for (int q = 0; q < 16; q++) {
            int i = tid * 16 + q;
            unsigned char b = msk[i];
            if (b == 0x3F) { f1 = 1; if ((i & 3) == 1) f0 = 1; }
            else if (b != 0 && (i & 3) != 0) f2 = 1;
        }
        if (f0) atomicOr(&flags[0], 1);
        if (f1) atomicOr(&flags[1], 1);
        if (f2) atomicOr(&flags[2], 1);
        __syncthreads();
        if (tid == 0) {
            int mode;
            if (flags[0])      mode = 3;
            else if (flags[1]) mode = 2;
            else if (flags[2]) mode = 1;
            else               mode = 0;
            g_mask_mode = mode;
        }
        return;
    }

    extern __shared__ char smem[];
    const uint32_t sb = smem_to_u32(smem);
    float* s1 = (float*)(smem + A_PAR);
    float* t1 = s1 + 256; float* s2 = t1 + 256; float* u2 = s2 + 64;

    const int lane = tid & 31, wid = tid >> 5;
    {
        float s = g1[tid] * rsqrtf(va1[tid] + EPS);
        s1[tid] = s; t1[tid] = be1[tid] - mu1[tid] * s;
    }
    if (tid < 64) {
        float s = g2[tid] * rsqrtf(va2[tid] + EPS);
        s2[tid] = s;
        u2[tid] = b1[tid] * s + (be2[tid] - mu2[tid] * s);
    }

    const int m0 = blockIdx.x * 128;
    const int row = tid >> 1, half = tid & 1;
    const float4* xr4 = reinterpret_cast<const float4*>(
        x + (size_t)(m0 + row) * CIN + half * 32);
    const uint32_t aoff = a_off(wid * 16, lane), boff = b_off(lane);
    float acc[8][4] = {};

    float4 xbuf[8];
    #pragma unroll
    for (int q = 0; q < 8; q++) xbuf[q] = xr4[q];
    copy_tile_async(sb + A_B0, g_w1t, tid); CP_COMMIT();   // B(0)

    for (int ch = 0; ch < 4; ch++) {
        __syncthreads();                 // gemm(ch-1) done; A + B[(ch+1)&1] free
        // A tile from prefetched regs: bn1+relu+split
        #pragma unroll
        for (int q = 0; q < 8; q++) {
            float4 v = xbuf[q];
            int cg = ch * 64 + half * 32 + q * 4;
            float a0 = fmaxf(v.x * s1[cg+0] + t1[cg+0], 0.0f);
            float a1 = fmaxf(v.y * s1[cg+1] + t1[cg+1], 0.0f);
            float a2 = fmaxf(v.z * s1[cg+2] + t1[cg+2], 0.0f);
            float a3 = fmaxf(v.w * s1[cg+3] + t1[cg+3], 0.0f);
            uint32_t h01, l01, h23, l23;
            split2(a0, a1, h01, l01); split2(a2, a3, h23, l23);
            int bo = row * ASTRIDE + half * 64 + q * 8;
            *(uint32_t*)(smem + A_AHI + bo)     = h01;
            *(uint32_t*)(smem + A_AHI + bo + 4) = h23;
            *(uint32_t*)(smem + A_ALO + bo)     = l01;
            *(uint32_t*)(smem + A_ALO + bo + 4) = l23;
        }
        if (ch < 3) {
            copy_tile_async(sb + ((ch + 1) & 1 ? A_B1 : A_B0),
                            g_w1t + (ch + 1) * 1152, tid);
            CP_COMMIT();
            #pragma unroll
            for (int q = 0; q < 8; q++) xbuf[q] = xr4[(ch + 1) * 16 + q];
            CP_WAIT1();
        } else {
            CP_WAIT0();
        }
        __syncthreads();
        const uint32_t bb = (ch & 1) ? A_B1 : A_B0;
        gemm_chunk16(sb, A_AHI, A_ALO, bb, bb + 9216, aoff, boff, acc);
    }

    const int r0 = m0 + wid * 16 + (lane >> 2);
    #pragma unroll
    for (int nt = 0; nt < 8; nt++) {
        int c0 = nt * 8 + (lane & 3) * 2;
        float v00 = fmaxf(acc[nt][0] * s2[c0]   + u2[c0],   0.0f);
        float v01 = fmaxf(acc[nt][1] * s2[c0+1] + u2[c0+1], 0.0f);
        float v10 = fmaxf(acc[nt][2] * s2[c0]   + u2[c0],   0.0f);
        float v11 = fmaxf(acc[nt][3] * s2[c0+1] + u2[c0+1], 0.0f);
        uint32_t h0, l0, h1, l1;
        split2(v00, v01, h0, l0); split2(v10, v11, h1, l1);
        *(uint32_t*)(g_h2hi + (size_t)r0 * MID + c0)     = h0;
        *(uint32_t*)(g_h2lo + (size_t)r0 * MID + c0)     = l0;
        *(uint32_t*)(g_h2hi + (size_t)(r0+8) * MID + c0) = h1;
        *(uint32_t*)(g_h2lo + (size_t)(r0+8) * MID + c0) = l1;
    }
}

// ---------------------------------------------------------------------------
// Fused kBC: phase 1 = gather-GEMM over 9 offsets (cp.async A + B tiles),
// phase 2 = h4 (in smem) @ w3 + b3 + shortcut with ping-pong B prefetch.
// ---------------------------------------------------------------------------
#define F_A0HI 0
#define F_A0LO 18432
#define F_A1HI 36864   /* phase 2: P1 hi 36864, lo 46080 */
#define F_A1LO 55296
#define F_B    73728   /* hi 73728, lo 82944 ; phase 2: P0 */
#define F_PAR  92160

__global__ void __launch_bounds__(256)
kBC(const float* __restrict__ x,
    const float* __restrict__ g1, const float* __restrict__ be1,
    const float* __restrict__ mu1, const float* __restrict__ va1,
    const float* __restrict__ b2,
    const float* __restrict__ g3, const float* __restrict__ be3,
    const float* __restrict__ mu3, const float* __restrict__ va3,
    const float* __restrict__ b3,
    const int* __restrict__ nbr, const void* __restrict__ maskp,
    float* __restrict__ out)
{
    extern __shared__ char smem[];
    const uint32_t sb = smem_to_u32(smem);
    float* s3  = (float*)(smem + F_PAR);        // [64]
    float* u3  = s3 + 64;                       // [64]
    float* s1a = u3 + 64;                       // [256]
    float* t1a = s1a + 256;                     // [256]
    float* b3a = t1a + 256;                     // [256]

    const int tid = threadIdx.x, lane = tid & 31, wid = tid >> 5;
    if (tid < 64) {
        float s = g3[tid] * rsqrtf(va3[tid] + EPS);
        s3[tid] = s;
        u3[tid] = b2[tid] * s + (be3[tid] - mu3[tid] * s);
    }
    {
        float s = g1[tid] * rsqrtf(va1[tid] + EPS);
        s1a[tid] = s; t1a[tid] = be1[tid] - mu1[tid] * s; b3a[tid] = b3[tid];
    }

    const int m0 = blockIdx.x * 128;
    const int row = tid >> 1, half = tid & 1;
    const int mode = g_mask_mode;
    const uint32_t aoff = a_off(wid * 16, lane), boff = b_off(lane);
    const size_t eb = (size_t)(m0 + row) * KOFF;

    auto issue_gather_with = [&](int idx, bool on, int buf) {
        uint32_t sz = on ? 16u : 0u;
        const char* hp = (const char*)(g_h2hi + (size_t)idx * MID + half * 32);
        const char* lp = (const char*)(g_h2lo + (size_t)idx * MID + half * 32);
        uint32_t dh = sb + (buf ? F_A1HI : F_A0HI) + row * ASTRIDE + half * 64;
        uint32_t dl = sb + (buf ? F_A1LO : F_A0LO) + row * ASTRIDE + half * 64;
        #pragma unroll
        for (int q = 0; q < 4; q++) {
            CP_ASYNC16(dh + q * 16, hp + q * 16, sz);
            CP_ASYNC16(dl + q * 16, lp + q * 16, sz);
        }
        CP_COMMIT();
    };

    float acc[8][4] = {};
    // prologue: gather(0) + next-iter idx/mask register double-buffer
    issue_gather_with(nbr[eb], mask_on(maskp, eb, mode), 0);
    int  nidx = nbr[eb + 1];
    bool non  = mask_on(maskp, eb + 1, mode);

    // ---------------- Phase 1: 9 gather chunks ----------------
    for (int k = 0; k < KOFF; k++) {
        __syncthreads();                // gemm(k-1) done: F_B + A[(k+1)&1] free
        copy_tile_async(sb + F_B, g_w2t + k * 1152, tid); CP_COMMIT();
        if (k < KOFF - 1) {
            issue_gather_with(nidx, non, (k + 1) & 1);
            if (k < KOFF - 2) {         // load idx/mask for k+2, hidden by gemm
                nidx = nbr[eb + k + 2];
                non  = mask_on(maskp, eb + k + 2, mode);
            }
            CP_WAIT1();                 // gather(k) + B(k) done; gather(k+1) pending
        } else {
            // prefetch w3 slice 0 into P1 (A1 region, free after gemm(7))
            copy_tile_async(sb + F_A1HI, g_w3t, tid); CP_COMMIT();
            CP_WAIT1();                 // gather(8) + B(8) done; w3(0) pending
        }
        __syncthreads();
        gemm_chunk16(sb, (k & 1) ? F_A1HI : F_A0HI, (k & 1) ? F_A1LO : F_A0LO,
                     F_B, F_B + 9216, aoff, boff, acc);
    }

    // ---------------- Transition: h4 = relu(bn3(acc)) -> A0 ----------------
    __syncthreads();
    {
        const int rl = wid * 16 + (lane >> 2);
        #pragma unroll
        for (int nt = 0; nt < 8; nt++) {
            int c0 = nt * 8 + (lane & 3) * 2;
            #pragma unroll
            for (int rr = 0; rr < 2; rr++) {
                int r = rl + rr * 8;
                const float* a = acc[nt] + rr * 2;
                float v0 = fmaxf(a[0] * s3[c0]   + u3[c0],   0.0f);
                float v1 = fmaxf(a[1] * s3[c0+1] + u3[c0+1], 0.0f);
                uint32_t h, l; split2(v0, v1, h, l);
                int bo = r * ASTRIDE + c0 * 2;
                *(uint32_t*)(smem + F_A0HI + bo) = h;
                *(uint32_t*)(smem + F_A0LO + bo) = l;
            }
        }
    }

    // ---------------- Phase 2: 4 col slices, B ping-pong P1/P0 ----------------
    const int rbase = m0 + wid * 16 + (lane >> 2);
    for (int s = 0; s < 4; s++) {
        __syncthreads();                // s=0: h4 STS done; s>0: gemm2(s-1) done
        if (s < 3) {
            // slice s+1 -> P((s+1)&1): odd->P0(F_B), even->P1(A1)
            uint32_t dst = ((s + 1) & 1) ? F_B : F_A1HI;
            copy_tile_async(sb + dst, g_w3t + (s + 1) * 1152, tid); CP_COMMIT();
            CP_WAIT1();                 // w3(s) done; w3(s+1) pending
        } else {
            CP_WAIT0();
        }
        __syncthreads();
        const uint32_t bb = (s & 1) ? F_B : F_A1HI;
        float acc2[8][4] = {};
        gemm_chunk16(sb, F_A0HI, F_A0LO, bb, bb + 9216, aoff, boff, acc2);

        #pragma unroll
        for (int nt = 0; nt < 8; nt++) {
            int lc = nt * 8 + (lane & 3) * 2;
            int c = s * 64 + lc;
            #pragma unroll
            for (int rr = 0; rr < 2; rr++) {
                int r = rbase + rr * 8;
                const float* a = acc2[nt] + rr * 2;
                float2 xv = *reinterpret_cast<const float2*>(x + (size_t)r * CIN + c);
                float o0 = a[0] + b3a[c]   + fmaxf(xv.x * s1a[c]   + t1a[c],   0.0f);
                float o1 = a[1] + b3a[c+1] + fmaxf(xv.y * s1a[c+1] + t1a[c+1], 0.0f);
                *reinterpret_cast<float2*>(out + (size_t)r * CIN + c) = make_float2(o0, o1);
            }
        }
    }
}

// ---------------------------------------------------------------------------
extern "C" void kernel_launch(void* const* d_in, const int* in_sizes, int n_in,
                              void* d_out, int out_size)
{
    const float* x     = (const float*)d_in[0];
    const float* bn1_g = (const float*)d_in[1];
    const float* bn1_b = (const float*)d_in[2];
    const float* bn1_m = (const float*)d_in[3];
    const float* bn1_v = (const float*)d_in[4];
    const float* w1    = (const float*)d_in[5];
    const float* b1    = (const float*)d_in[6];
    const float* bn2_g = (const float*)d_in[7];
    const float* bn2_b = (const float*)d_in[8];
    const float* bn2_m = (const float*)d_in[9];
    const float* bn2_v = (const float*)d_in[10];
    const float* w2    = (const float*)d_in[11];
    const float* b2    = (const float*)d_in[12];
    const float* bn3_g = (const float*)d_in[13];
    const float* bn3_b = (const float*)d_in[14];
    const float* bn3_m = (const float*)d_in[15];
    const float* bn3_v = (const float*)d_in[16];
    const float* w3    = (const float*)d_in[17];
    const float* b3    = (const float*)d_in[18];
    const int*   nbr   = (const int*)d_in[19];
    const void*  msk   = (const void*)d_in[20];
    float* out = (float*)d_out;

    const int SMA  = A_PAR + (256 + 256 + 64 + 64) * 4;
    const int SMBC = F_PAR + (64 + 64 + 256 + 256 + 256) * 4;
    cudaFuncSetAttribute(kA,  cudaFuncAttributeMaxDynamicSharedMemorySize, SMA);
    cudaFuncSetAttribute(kBC, cudaFuncAttributeMaxDynamicSharedMemorySize, SMBC);

    kPrep<<<17, 256>>>(w1, w2, w3);
    kA<<<NROWS / 128 + 1, 256, SMA>>>(x, bn1_g, bn1_b, bn1_m, bn1_v, b1,
                                      bn2_g, bn2_b, bn2_m, bn2_v,
                                      (const unsigned char*)msk);
    kBC<<<NROWS / 128, 256, SMBC>>>(x, bn1_g, bn1_b, bn1_m, bn1_v,
                                    b2, bn3_g, bn3_b, bn3_m, bn3_v,
                                    b3, nbr, msk, out);
    (void)in_sizes; (void)n_in; (void)out_size;
}

// round 9
// speedup vs baseline: 1.2445x; 1.2445x over previous
#include <cuda_runtime.h>
#include <cuda_bf16.h>
#include <cstdint>

#define NROWS 262144
#define CIN   256
#define MID   64
#define KOFF  9
#define EPS   1e-5f

// Pre-split bf16 tables for h2 (device globals; no allocs allowed).
__device__ unsigned short g_h2hi[(size_t)NROWS * MID];
__device__ unsigned short g_h2lo[(size_t)NROWS * MID];
__device__ int g_mask_mode;

__device__ __forceinline__ uint32_t smem_to_u32(const void* p) {
    uint32_t a;
    asm("{ .reg .u64 t; cvta.to.shared.u64 t, %1; cvt.u32.u64 %0, t; }"
        : "=r"(a) : "l"(p));
    return a;
}

#define LDSM4(r, a)                                                            \
    asm volatile("ldmatrix.sync.aligned.m8n8.x4.shared.b16 {%0,%1,%2,%3}, [%4];" \
        : "=r"((r)[0]), "=r"((r)[1]), "=r"((r)[2]), "=r"((r)[3]) : "r"(a))

#define MMA_BF16(d, a, b)                                                      \
    asm volatile("mma.sync.aligned.m16n8k16.row.col.f32.bf16.bf16.f32 "        \
        "{%0,%1,%2,%3}, {%4,%5,%6,%7}, {%8,%9}, {%0,%1,%2,%3};"                \
        : "+f"((d)[0]), "+f"((d)[1]), "+f"((d)[2]), "+f"((d)[3])               \
        : "r"((a)[0]), "r"((a)[1]), "r"((a)[2]), "r"((a)[3]),                  \
          "r"((b)[0]), "r"((b)[1]))

#define CP_ASYNC16(dst, src, sz)                                               \
    asm volatile("cp.async.cg.shared.global [%0], [%1], 16, %2;"               \
                 :: "r"(dst), "l"(src), "r"(sz))
#define CP_COMMIT() asm volatile("cp.async.commit_group;" ::: "memory")
#define CP_WAIT0()  asm volatile("cp.async.wait_group 0;" ::: "memory")

__device__ __forceinline__ void split2(float v0, float v1, uint32_t& hi, uint32_t& lo) {
    __nv_bfloat16 h0 = __float2bfloat16(v0), h1 = __float2bfloat16(v1);
    __nv_bfloat16 l0 = __float2bfloat16(v0 - __bfloat162float(h0));
    __nv_bfloat16 l1 = __float2bfloat16(v1 - __bfloat162float(h1));
    hi = (uint32_t)__bfloat16_as_ushort(h0) | ((uint32_t)__bfloat16_as_ushort(h1) << 16);
    lo = (uint32_t)__bfloat16_as_ushort(l0) | ((uint32_t)__bfloat16_as_ushort(l1) << 16);
}
__device__ __forceinline__ void split1(float v, unsigned short& h, unsigned short& l) {
    __nv_bfloat16 hb = __float2bfloat16(v);
    __nv_bfloat16 lb = __float2bfloat16(v - __bfloat162float(hb));
    h = __bfloat16_as_ushort(hb); l = __bfloat16_as_ushort(lb);
}

__device__ __forceinline__ bool mask_on(const void* p, size_t i, int mode) {
    switch (mode) {
        case 1:  return ((const unsigned char*)p)[i] != 0;
        case 2:  return ((const float*)p)[i] != 0.0f;
        case 3:  return ((const unsigned short*)p)[i] != 0;
        default: return ((const int*)p)[i] != 0;
    }
}

#define ASTRIDE 144

// ---- 16x64 warp tile (R4-proven, used by kA) ----
__device__ __forceinline__ void gemm_chunk16(uint32_t sb, uint32_t ahi, uint32_t alo,
                                             uint32_t bhi, uint32_t blo,
                                             uint32_t aoff, uint32_t boff,
                                             float acc[8][4]) {
    #pragma unroll
    for (int ks = 0; ks < 4; ks++) {
        uint32_t ah[4], al[4];
        LDSM4(ah, sb + ahi + aoff + ks * 32);
        LDSM4(al, sb + alo + aoff + ks * 32);
        uint32_t bh[16], bl[16];
        #pragma unroll
        for (int p = 0; p < 4; p++) {
            LDSM4(bh + 4 * p, sb + bhi + boff + p * (16 * ASTRIDE) + ks * 32);
            LDSM4(bl + 4 * p, sb + blo + boff + p * (16 * ASTRIDE) + ks * 32);
        }
        #pragma unroll
        for (int nt = 0; nt < 8; nt++) {
            const uint32_t* fh = bh + (nt >> 1) * 4 + (nt & 1) * 2;
            const uint32_t* fl = bl + (nt >> 1) * 4 + (nt & 1) * 2;
            MMA_BF16(acc[nt], ah, fh);
            MMA_BF16(acc[nt], ah, fl);
            MMA_BF16(acc[nt], al, fh);
        }
    }
}

// ---- 32x64 warp tile (R5-verified math, used by kBC) ----
__device__ __forceinline__ void gemm_chunk32(uint32_t sb, uint32_t ahi, uint32_t alo,
                                             uint32_t bhi, uint32_t blo,
                                             uint32_t aoff, uint32_t boff,
                                             float acc[2][8][4]) {
    #pragma unroll
    for (int ks = 0; ks < 4; ks++) {
        uint32_t ah0[4], al0[4], ah1[4], al1[4];
        LDSM4(ah0, sb + ahi + aoff + ks * 32);
        LDSM4(ah1, sb + ahi + aoff + 16 * ASTRIDE + ks * 32);
        LDSM4(al0, sb + alo + aoff + ks * 32);
        LDSM4(al1, sb + alo + aoff + 16 * ASTRIDE + ks * 32);
        uint32_t bh[16], bl[16];
        #pragma unroll
        for (int p = 0; p < 4; p++) {
            LDSM4(bh + 4 * p, sb + bhi + boff + p * (16 * ASTRIDE) + ks * 32);
            LDSM4(bl + 4 * p, sb + blo + boff + p * (16 * ASTRIDE) + ks * 32);
        }
        #pragma unroll
        for (int nt = 0; nt < 8; nt++) {
            const uint32_t* fh = bh + (nt >> 1) * 4 + (nt & 1) * 2;
            const uint32_t* fl = bl + (nt >> 1) * 4 + (nt & 1) * 2;
            MMA_BF16(acc[0][nt], ah0, fh);
            MMA_BF16(acc[1][nt], ah1, fh);
            MMA_BF16(acc[0][nt], ah0, fl);
            MMA_BF16(acc[1][nt], ah1, fl);
            MMA_BF16(acc[0][nt], al0, fh);
            MMA_BF16(acc[1][nt], al1, fh);
        }
    }
}

// Transpose a [64k x 64n] f32 weight chunk into split-bf16 B tiles [n][k].
__device__ __forceinline__ void build_B256(char* smem, uint32_t bhi, uint32_t blo,
                                           const float* __restrict__ wsrc,
                                           int ldw, int tid) {
    const int kr = tid >> 2, ns = (tid & 3) * 16;
    const float4* wr = reinterpret_cast<const float4*>(wsrc + (size_t)kr * ldw + ns);
    #pragma unroll
    for (int q = 0; q < 4; q++) {
        float4 v = wr[q];
        float e[4] = {v.x, v.y, v.z, v.w};
        #pragma unroll
        for (int j = 0; j < 4; j++) {
            int n = ns + q * 4 + j;
            unsigned short h, l; split1(e[j], h, l);
            *(unsigned short*)(smem + bhi + n * ASTRIDE + kr * 2) = h;
            *(unsigned short*)(smem + blo + n * ASTRIDE + kr * 2) = l;
        }
    }
}
__device__ __forceinline__ void build_B128(char* smem, uint32_t bhi, uint32_t blo,
                                           const float* __restrict__ wsrc,
                                           int ldw, int tid) {
    const int kr = tid >> 1, ns = (tid & 1) * 32;
    const float4* wr = reinterpret_cast<const float4*>(wsrc + (size_t)kr * ldw + ns);
    #pragma unroll
    for (int q = 0; q < 8; q++) {
        float4 v = wr[q];
        float e[4] = {v.x, v.y, v.z, v.w};
        #pragma unroll
        for (int j = 0; j < 4; j++) {
            int n = ns + q * 4 + j;
            unsigned short h, l; split1(e[j], h, l);
            *(unsigned short*)(smem + bhi + n * ASTRIDE + kr * 2) = h;
            *(unsigned short*)(smem + blo + n * ASTRIDE + kr * 2) = l;
        }
    }
}

__device__ __forceinline__ uint32_t a_off(int wr0, int lane) {
    int row = wr0 + (lane & 7) + ((lane >> 3) & 1) * 8;
    return row * ASTRIDE + (lane >> 4) * 16;
}
__device__ __forceinline__ uint32_t b_off(int lane) {
    int n = (lane & 7) + (lane >> 4) * 8;
    return n * ASTRIDE + ((lane >> 3) & 1) * 16;
}

// ---------------------------------------------------------------------------
// Kernel A (R7-identical GEMM path): h2 = relu(bn2( relu(bn1(x)) @ w1 + b1 )).
// BM=128, 256 threads, 16x64 warp tile, x reg-prefetch. Last block = detection.
// ---------------------------------------------------------------------------
#define A_AHI 0
#define A_ALO 18432
#define A_BHI 36864
#define A_BLO 46080
#define A_PAR 55296

__global__ void __launch_bounds__(256)
kA(const float* __restrict__ x,
   const float* __restrict__ g1, const float* __restrict__ be1,
   const float* __restrict__ mu1, const float* __restrict__ va1,
   const float* __restrict__ w1, const float* __restrict__ b1,
   const float* __restrict__ g2, const float* __restrict__ be2,
   const float* __restrict__ mu2, const float* __restrict__ va2,
   const unsigned char* __restrict__ msk)
{
    const int tid = threadIdx.x;

    if (blockIdx.x == NROWS / 128) {   // detection block
        __shared__ int flags[3];
        if (tid < 3) flags[tid] = 0;
        __syncthreads();
        int f0 = 0, f1 = 0, f2 = 0;
        #pragma unroll
        for (int q = 0; q < 16; q++) {
            int i = tid * 16 + q;
            unsigned char b = msk[i];
            if (b == 0x3F) { f1 = 1; if ((i & 3) == 1) f0 = 1; }
            else if (b != 0 && (i & 3) != 0) f2 = 1;
        }
        if (f0) atomicOr(&flags[0], 1);
        if (f1) atomicOr(&flags[1], 1);
        if (f2) atomicOr(&flags[2], 1);
        __syncthreads();
        if (tid == 0) {
            int mode;
            if (flags[0])      mode = 3;
            else if (flags[1]) mode = 2;
            else if (flags[2]) mode = 1;
            else               mode = 0;
            g_mask_mode = mode;
        }
        return;
    }

    extern __shared__ char smem[];
    const uint32_t sb = smem_to_u32(smem);
    float* s1 = (float*)(smem + A_PAR);
    float* t1 = s1 + 256; float* s2 = t1 + 256; float* u2 = s2 + 64;

    const int lane = tid & 31, wid = tid >> 5;
    {
        float s = g1[tid] * rsqrtf(va1[tid] + EPS);
        s1[tid] = s; t1[tid] = be1[tid] - mu1[tid] * s;
    }
    if (tid < 64) {
        float s = g2[tid] * rsqrtf(va2[tid] + EPS);
        s2[tid] = s;
        u2[tid] = b1[tid] * s + (be2[tid] - mu2[tid] * s);
    }

    const int m0 = blockIdx.x * 128;
    const int row = tid >> 1, half = tid & 1;
    const float4* xr4 = reinterpret_cast<const float4*>(
        x + (size_t)(m0 + row) * CIN + half * 32);
    const uint32_t aoff = a_off(wid * 16, lane), boff = b_off(lane);
    float acc[8][4] = {};

    float4 xbuf[8];
    #pragma unroll
    for (int q = 0; q < 8; q++) xbuf[q] = xr4[q];

    for (int ch = 0; ch < 4; ch++) {
        __syncthreads();
        #pragma unroll
        for (int q = 0; q < 8; q++) {
            float4 v = xbuf[q];
            int cg = ch * 64 + half * 32 + q * 4;
            float a0 = fmaxf(v.x * s1[cg+0] + t1[cg+0], 0.0f);
            float a1 = fmaxf(v.y * s1[cg+1] + t1[cg+1], 0.0f);
            float a2 = fmaxf(v.z * s1[cg+2] + t1[cg+2], 0.0f);
            float a3 = fmaxf(v.w * s1[cg+3] + t1[cg+3], 0.0f);
            uint32_t h01, l01, h23, l23;
            split2(a0, a1, h01, l01); split2(a2, a3, h23, l23);
            int bo = row * ASTRIDE + half * 64 + q * 8;
            *(uint32_t*)(smem + A_AHI + bo)     = h01;
            *(uint32_t*)(smem + A_AHI + bo + 4) = h23;
            *(uint32_t*)(smem + A_ALO + bo)     = l01;
            *(uint32_t*)(smem + A_ALO + bo + 4) = l23;
        }
        build_B256(smem, A_BHI, A_BLO, w1 + (size_t)(ch * 64) * MID, MID, tid);
        __syncthreads();
        if (ch < 3) {
            #pragma unroll
            for (int q = 0; q < 8; q++) xbuf[q] = xr4[(ch + 1) * 16 + q];
        }
        gemm_chunk16(sb, A_AHI, A_ALO, A_BHI, A_BLO, aoff, boff, acc);
    }

    const int r0 = m0 + wid * 16 + (lane >> 2);
    #pragma unroll
    for (int nt = 0; nt < 8; nt++) {
        int c0 = nt * 8 + (lane & 3) * 2;
        float v00 = fmaxf(acc[nt][0] * s2[c0]   + u2[c0],   0.0f);
        float v01 = fmaxf(acc[nt][1] * s2[c0+1] + u2[c0+1], 0.0f);
        float v10 = fmaxf(acc[nt][2] * s2[c0]   + u2[c0],   0.0f);
        float v11 = fmaxf(acc[nt][3] * s2[c0+1] + u2[c0+1], 0.0f);
        uint32_t h0, l0, h1, l1;
        split2(v00, v01, h0, l0); split2(v10, v11, h1, l1);
        *(uint32_t*)(g_h2hi + (size_t)r0 * MID + c0)     = h0;
        *(uint32_t*)(g_h2lo + (size_t)r0 * MID + c0)     = l0;
        *(uint32_t*)(g_h2hi + (size_t)(r0+8) * MID + c0) = h1;
        *(uint32_t*)(g_h2lo + (size_t)(r0+8) * MID + c0) = l1;
    }
}

// ---------------------------------------------------------------------------
// Fused kBC: 128 threads, 4 warps, warp tile 32x64, 3 CTAs/SM target.
// Phase 1: 9 gather chunks (single A buffer, cp.async gather overlapped with
// build_B). Phase 2: h4 (in smem) @ w3 + b3 + shortcut, 4 col slices.
// ---------------------------------------------------------------------------
#define G_AHI 0
#define G_ALO 18432
#define G_B   36864   /* hi 36864, lo 46080 */
#define G_PAR 55296

__global__ void __launch_bounds__(128, 3)
kBC(const float* __restrict__ x,
    const float* __restrict__ g1, const float* __restrict__ be1,
    const float* __restrict__ mu1, const float* __restrict__ va1,
    const float* __restrict__ w2, const float* __restrict__ b2,
    const float* __restrict__ g3, const float* __restrict__ be3,
    const float* __restrict__ mu3, const float* __restrict__ va3,
    const float* __restrict__ w3, const float* __restrict__ b3,
    const int* __restrict__ nbr, const void* __restrict__ maskp,
    float* __restrict__ out)
{
    extern __shared__ char smem[];
    const uint32_t sb = smem_to_u32(smem);
    float* s3  = (float*)(smem + G_PAR);        // [64]
    float* u3  = s3 + 64;                       // [64]
    float* s1a = u3 + 64;                       // [256]
    float* t1a = s1a + 256;                     // [256]
    float* b3a = t1a + 256;                     // [256]

    const int tid = threadIdx.x, lane = tid & 31, wid = tid >> 5;
    if (tid < 64) {
        float s = g3[tid] * rsqrtf(va3[tid] + EPS);
        s3[tid] = s;
        u3[tid] = b2[tid] * s + (be3[tid] - mu3[tid] * s);
    }
    #pragma unroll
    for (int c = tid; c < 256; c += 128) {
        float s = g1[c] * rsqrtf(va1[c] + EPS);
        s1a[c] = s; t1a[c] = be1[c] - mu1[c] * s; b3a[c] = b3[c];
    }

    const int m0 = blockIdx.x * 128;
    const int mode = g_mask_mode;
    const uint32_t aoff = a_off(wid * 32, lane), boff = b_off(lane);
    const size_t eb = (size_t)(m0 + tid) * KOFF;   // one gather row per thread

    float acc[2][8][4] = {};
    int  nidx = nbr[eb];
    bool non  = mask_on(maskp, eb, mode);

    // ---------------- Phase 1: 9 gather chunks, single A buffer ----------------
    for (int k = 0; k < KOFF; k++) {
        __syncthreads();                 // gemm(k-1) done: A + B reusable
        // issue gather(k): one pre-split h2 row per thread (zero-fill if masked)
        {
            uint32_t sz = non ? 16u : 0u;
            const char* hp = (const char*)(g_h2hi + (size_t)nidx * MID);
            const char* lp = (const char*)(g_h2lo + (size_t)nidx * MID);
            uint32_t dh = sb + G_AHI + tid * ASTRIDE;
            uint32_t dl = sb + G_ALO + tid * ASTRIDE;
            #pragma unroll
            for (int q = 0; q < 8; q++) {
                CP_ASYNC16(dh + q * 16, hp + q * 16, sz);
                CP_ASYNC16(dl + q * 16, lp + q * 16, sz);
            }
            CP_COMMIT();
        }
        build_B128(smem, G_B, G_B + 9216, w2 + (size_t)k * 4096, MID, tid);
        if (k < KOFF - 1) {              // prefetch next idx/mask into regs
            nidx = nbr[eb + k + 1];
            non  = mask_on(maskp, eb + k + 1, mode);
        }
        CP_WAIT0();
        __syncthreads();
        gemm_chunk32(sb, G_AHI, G_ALO, G_B, G_B + 9216, aoff, boff, acc);
    }

    // ---------------- Transition: h4 = relu(bn3(acc)) -> A buffer ----------------
    __syncthreads();
    {
        const int rl = wid * 32 + (lane >> 2);
        #pragma unroll
        for (int nt = 0; nt < 8; nt++) {
            int c0 = nt * 8 + (lane & 3) * 2;
            #pragma unroll
            for (int rr = 0; rr < 4; rr++) {
                int r = rl + rr * 8;
                const float* a = acc[rr >> 1][nt] + (rr & 1) * 2;
                float v0 = fmaxf(a[0] * s3[c0]   + u3[c0],   0.0f);
                float v1 = fmaxf(a[1] * s3[c0+1] + u3[c0+1], 0.0f);
                uint32_t h, l; split2(v0, v1, h, l);
                int bo = r * ASTRIDE + c0 * 2;
                *(uint32_t*)(smem + G_AHI + bo) = h;
                *(uint32_t*)(smem + G_ALO + bo) = l;
            }
        }
    }

    // ---------------- Phase 2: 4 col slices of 64 ----------------
    const int rbase = m0 + wid * 32 + (lane >> 2);
    for (int s = 0; s < 4; s++) {
        __syncthreads();                 // h4 ready / prev gemm done with B
        build_B128(smem, G_B, G_B + 9216, w3 + s * 64, CIN, tid);
        __syncthreads();
        float acc2[2][8][4] = {};
        gemm_chunk32(sb, G_AHI, G_ALO, G_B, G_B + 9216, aoff, boff, acc2);

        #pragma unroll
        for (int nt = 0; nt < 8; nt++) {
            int lc = nt * 8 + (lane & 3) * 2;
            int c = s * 64 + lc;
            #pragma unroll
            for (int rr = 0; rr < 4; rr++) {
                int r = rbase + rr * 8;
                const float* a = acc2[rr >> 1][nt] + (rr & 1) * 2;
                float2 xv = *reinterpret_cast<const float2*>(x + (size_t)r * CIN + c);
                float o0 = a[0] + b3a[c]   + fmaxf(xv.x * s1a[c]   + t1a[c],   0.0f);
                float o1 = a[1] + b3a[c+1] + fmaxf(xv.y * s1a[c+1] + t1a[c+1], 0.0f);
                *reinterpret_cast<float2*>(out + (size_t)r * CIN + c) = make_float2(o0, o1);
            }
        }
    }
}

// ---------------------------------------------------------------------------
extern "C" void kernel_launch(void* const* d_in, const int* in_sizes, int n_in,
                              void* d_out, int out_size)
{
    const float* x     = (const float*)d_in[0];
    const float* bn1_g = (const float*)d_in[1];
    const float* bn1_b = (const float*)d_in[2];
    const float* bn1_m = (const float*)d_in[3];
    const float* bn1_v = (const float*)d_in[4];
    const float* w1    = (const float*)d_in[5];
    const float* b1    = (const float*)d_in[6];
    const float* bn2_g = (const float*)d_in[7];
    const float* bn2_b = (const float*)d_in[8];
    const float* bn2_m = (const float*)d_in[9];
    const float* bn2_v = (const float*)d_in[10];
    const float* w2    = (const float*)d_in[11];
    const float* b2    = (const float*)d_in[12];
    const float* bn3_g = (const float*)d_in[13];
    const float* bn3_b = (const float*)d_in[14];
    const float* bn3_m = (const float*)d_in[15];
    const float* bn3_v = (const float*)d_in[16];
    const float* w3    = (const float*)d_in[17];
    const float* b3    = (const float*)d_in[18];
    const int*   nbr   = (const int*)d_in[19];
    const void*  msk   = (const void*)d_in[20];
    float* out = (float*)d_out;

    const int SMA  = A_PAR + (256 + 256 + 64 + 64) * 4;
    const int SMBC = G_PAR + (64 + 64 + 256 + 256 + 256) * 4;
    cudaFuncSetAttribute(kA,  cudaFuncAttributeMaxDynamicSharedMemorySize, SMA);
    cudaFuncSetAttribute(kBC, cudaFuncAttributeMaxDynamicSharedMemorySize, SMBC);

    kA<<<NROWS / 128 + 1, 256, SMA>>>(x, bn1_g, bn1_b, bn1_m, bn1_v, w1, b1,
                                      bn2_g, bn2_b, bn2_m, bn2_v,
                                      (const unsigned char*)msk);
    kBC<<<NROWS / 128, 128, SMBC>>>(x, bn1_g, bn1_b, bn1_m, bn1_v,
                                    w2, b2, bn3_g, bn3_b, bn3_m, bn3_v,
                                    w3, b3, nbr, msk, out);
    (void)in_sizes; (void)n_in; (void)out_size;
}

// round 10
// speedup vs baseline: 1.5073x; 1.2112x over previous
#include <cuda_runtime.h>
#include <cuda_bf16.h>
#include <cstdint>

#define NROWS 262144
#define CIN   256
#define MID   64
#define KOFF  9
#define EPS   1e-5f

// Pre-split bf16 tables for h2 (device globals; no allocs allowed).
__device__ unsigned short g_h2hi[(size_t)NROWS * MID];
__device__ unsigned short g_h2lo[(size_t)NROWS * MID];
__device__ int g_mask_mode;

// Pre-split w2/w3 tiles in exact smem image: 18432 B = [hi 64x144][lo 64x144].
__device__ uint4 g_w2t[9 * 1152];
__device__ uint4 g_w3t[4 * 1152];

__device__ __forceinline__ uint32_t smem_to_u32(const void* p) {
    uint32_t a;
    asm("{ .reg .u64 t; cvta.to.shared.u64 t, %1; cvt.u32.u64 %0, t; }"
        : "=r"(a) : "l"(p));
    return a;
}

#define LDSM4(r, a)                                                            \
    asm volatile("ldmatrix.sync.aligned.m8n8.x4.shared.b16 {%0,%1,%2,%3}, [%4];" \
        : "=r"((r)[0]), "=r"((r)[1]), "=r"((r)[2]), "=r"((r)[3]) : "r"(a))

#define MMA_BF16(d, a, b)                                                      \
    asm volatile("mma.sync.aligned.m16n8k16.row.col.f32.bf16.bf16.f32 "        \
        "{%0,%1,%2,%3}, {%4,%5,%6,%7}, {%8,%9}, {%0,%1,%2,%3};"                \
        : "+f"((d)[0]), "+f"((d)[1]), "+f"((d)[2]), "+f"((d)[3])               \
        : "r"((a)[0]), "r"((a)[1]), "r"((a)[2]), "r"((a)[3]),                  \
          "r"((b)[0]), "r"((b)[1]))

#define CP_ASYNC16(dst, src, sz)                                               \
    asm volatile("cp.async.cg.shared.global [%0], [%1], 16, %2;"               \
                 :: "r"(dst), "l"(src), "r"(sz))
#define CP_COMMIT() asm volatile("cp.async.commit_group;" ::: "memory")
#define CP_WAIT0()  asm volatile("cp.async.wait_group 0;" ::: "memory")

__device__ __forceinline__ void split2(float v0, float v1, uint32_t& hi, uint32_t& lo) {
    __nv_bfloat16 h0 = __float2bfloat16(v0), h1 = __float2bfloat16(v1);
    __nv_bfloat16 l0 = __float2bfloat16(v0 - __bfloat162float(h0));
    __nv_bfloat16 l1 = __float2bfloat16(v1 - __bfloat162float(h1));
    hi = (uint32_t)__bfloat16_as_ushort(h0) | ((uint32_t)__bfloat16_as_ushort(h1) << 16);
    lo = (uint32_t)__bfloat16_as_ushort(l0) | ((uint32_t)__bfloat16_as_ushort(l1) << 16);
}
__device__ __forceinline__ void split1(float v, unsigned short& h, unsigned short& l) {
    __nv_bfloat16 hb = __float2bfloat16(v);
    __nv_bfloat16 lb = __float2bfloat16(v - __bfloat162float(hb));
    h = __bfloat16_as_ushort(hb); l = __bfloat16_as_ushort(lb);
}

__device__ __forceinline__ bool mask_on(const void* p, size_t i, int mode) {
    switch (mode) {
        case 1:  return ((const unsigned char*)p)[i] != 0;
        case 2:  return ((const float*)p)[i] != 0.0f;
        case 3:  return ((const unsigned short*)p)[i] != 0;
        default: return ((const int*)p)[i] != 0;
    }
}

#define ASTRIDE 144

// ---- 32x64 warp tile over one 64-deep K chunk (R9-proven) ----
__device__ __forceinline__ void gemm_chunk32(uint32_t sb, uint32_t ahi, uint32_t alo,
                                             uint32_t bhi, uint32_t blo,
                                             uint32_t aoff, uint32_t boff,
                                             float acc[2][8][4]) {
    #pragma unroll
    for (int ks = 0; ks < 4; ks++) {
        uint32_t ah0[4], al0[4], ah1[4], al1[4];
        LDSM4(ah0, sb + ahi + aoff + ks * 32);
        LDSM4(ah1, sb + ahi + aoff + 16 * ASTRIDE + ks * 32);
        LDSM4(al0, sb + alo + aoff + ks * 32);
        LDSM4(al1, sb + alo + aoff + 16 * ASTRIDE + ks * 32);
        uint32_t bh[16], bl[16];
        #pragma unroll
        for (int p = 0; p < 4; p++) {
            LDSM4(bh + 4 * p, sb + bhi + boff + p * (16 * ASTRIDE) + ks * 32);
            LDSM4(bl + 4 * p, sb + blo + boff + p * (16 * ASTRIDE) + ks * 32);
        }
        #pragma unroll
        for (int nt = 0; nt < 8; nt++) {
            const uint32_t* fh = bh + (nt >> 1) * 4 + (nt & 1) * 2;
            const uint32_t* fl = bl + (nt >> 1) * 4 + (nt & 1) * 2;
            MMA_BF16(acc[0][nt], ah0, fh);
            MMA_BF16(acc[1][nt], ah1, fh);
            MMA_BF16(acc[0][nt], ah0, fl);
            MMA_BF16(acc[1][nt], ah1, fl);
            MMA_BF16(acc[0][nt], al0, fh);
            MMA_BF16(acc[1][nt], al1, fh);
        }
    }
}

// Transpose a [64k x 64n] f32 weight chunk into split-bf16 B tiles (128 thr).
__device__ __forceinline__ void build_B128(char* smem, uint32_t bhi, uint32_t blo,
                                           const float* __restrict__ wsrc,
                                           int ldw, int tid) {
    const int kr = tid >> 1, ns = (tid & 1) * 32;
    const float4* wr = reinterpret_cast<const float4*>(wsrc + (size_t)kr * ldw + ns);
    #pragma unroll
    for (int q = 0; q < 8; q++) {
        float4 v = wr[q];
        float e[4] = {v.x, v.y, v.z, v.w};
        #pragma unroll
        for (int j = 0; j < 4; j++) {
            int n = ns + q * 4 + j;
            unsigned short h, l; split1(e[j], h, l);
            *(unsigned short*)(smem + bhi + n * ASTRIDE + kr * 2) = h;
            *(unsigned short*)(smem + blo + n * ASTRIDE + kr * 2) = l;
        }
    }
}

// Coalesced async copy of one 18432-B prepped tile into smem (128 thr).
__device__ __forceinline__ void copy_tile128(uint32_t dst, const uint4* src, int tid) {
    #pragma unroll
    for (int i = 0; i < 9; i++)
        CP_ASYNC16(dst + (i * 128 + tid) * 16, (const char*)(src + i * 128 + tid), 16);
}

__device__ __forceinline__ uint32_t a_off(int wr0, int lane) {
    int row = wr0 + (lane & 7) + ((lane >> 3) & 1) * 8;
    return row * ASTRIDE + (lane >> 4) * 16;
}
__device__ __forceinline__ uint32_t b_off(int lane) {
    int n = (lane & 7) + (lane >> 4) * 8;
    return n * ASTRIDE + ((lane >> 3) & 1) * 16;
}

// ---------------------------------------------------------------------------
// Kernel A: h2 = relu(bn2( relu(bn1(x)) @ w1 + b1 )). BM=128, 128 threads,
// warp tile 32x64, 3 CTAs/SM. Extra blocks: 13 = prep w2/w3 tiles, 1 = detect.
// ---------------------------------------------------------------------------
#define A_AHI 0
#define A_ALO 18432
#define A_BHI 36864
#define A_BLO 46080
#define A_PAR 55296

__global__ void __launch_bounds__(128, 3)
kA(const float* __restrict__ x,
   const float* __restrict__ g1, const float* __restrict__ be1,
   const float* __restrict__ mu1, const float* __restrict__ va1,
   const float* __restrict__ w1, const float* __restrict__ b1,
   const float* __restrict__ g2, const float* __restrict__ be2,
   const float* __restrict__ mu2, const float* __restrict__ va2,
   const float* __restrict__ w2, const float* __restrict__ w3,
   const unsigned char* __restrict__ msk)
{
    const int tid = threadIdx.x;

    if (blockIdx.x >= NROWS / 128) {
        const int xb = blockIdx.x - NROWS / 128;
        if (xb < 13) {                       // prep one w2/w3 tile to global
            const float* src; int ldw; unsigned char* d8;
            if (xb < 9) { src = w2 + (size_t)xb * 4096; ldw = MID;
                          d8 = (unsigned char*)(g_w2t + xb * 1152); }
            else        { src = w3 + (xb - 9) * 64;     ldw = CIN;
                          d8 = (unsigned char*)(g_w3t + (xb - 9) * 1152); }
            const int kr = tid >> 1, ns = (tid & 1) * 32;
            const float4* wr = reinterpret_cast<const float4*>(src + (size_t)kr * ldw + ns);
            #pragma unroll
            for (int q = 0; q < 8; q++) {
                float4 v = wr[q];
                float e[4] = {v.x, v.y, v.z, v.w};
                #pragma unroll
                for (int j = 0; j < 4; j++) {
                    int n = ns + q * 4 + j;
                    unsigned short h, l; split1(e[j], h, l);
                    *(unsigned short*)(d8 + n * ASTRIDE + kr * 2)        = h;
                    *(unsigned short*)(d8 + 9216 + n * ASTRIDE + kr * 2) = l;
                }
            }
        } else {                             // mask dtype detection
            __shared__ int flags[3];
            if (tid < 3) flags[tid] = 0;
            __syncthreads();
            int f0 = 0, f1 = 0, f2 = 0;
            #pragma unroll
            for (int q = 0; q < 32; q++) {
                int i = tid * 32 + q;
                unsigned char b = msk[i];
                if (b == 0x3F) { f1 = 1; if ((i & 3) == 1) f0 = 1; }
                else if (b != 0 && (i & 3) != 0) f2 = 1;
            }
            if (f0) atomicOr(&flags[0], 1);
            if (f1) atomicOr(&flags[1], 1);
            if (f2) atomicOr(&flags[2], 1);
            __syncthreads();
            if (tid == 0) {
                int mode;
                if (flags[0])      mode = 3;
                else if (flags[1]) mode = 2;
                else if (flags[2]) mode = 1;
                else               mode = 0;
                g_mask_mode = mode;
            }
        }
        return;
    }

    extern __shared__ char smem[];
    const uint32_t sb = smem_to_u32(smem);
    float* s1 = (float*)(smem + A_PAR);
    float* t1 = s1 + 256; float* s2 = t1 + 256; float* u2 = s2 + 64;

    const int lane = tid & 31, wid = tid >> 5;
    #pragma unroll
    for (int c = tid; c < 256; c += 128) {
        float s = g1[c] * rsqrtf(va1[c] + EPS);
        s1[c] = s; t1[c] = be1[c] - mu1[c] * s;
    }
    if (tid < 64) {
        float s = g2[tid] * rsqrtf(va2[tid] + EPS);
        s2[tid] = s;
        u2[tid] = b1[tid] * s + (be2[tid] - mu2[tid] * s);
    }

    const int m0 = blockIdx.x * 128;
    const float4* xr4 = reinterpret_cast<const float4*>(x + (size_t)(m0 + tid) * CIN);
    const uint32_t aoff = a_off(wid * 32, lane), boff = b_off(lane);
    float acc[2][8][4] = {};

    for (int ch = 0; ch < 4; ch++) {
        __syncthreads();
        // A tile: one full 64-channel chunk per thread, bn1+relu+split
        #pragma unroll
        for (int q = 0; q < 16; q++) {
            float4 v = xr4[ch * 16 + q];
            int cg = ch * 64 + q * 4;
            float a0 = fmaxf(v.x * s1[cg+0] + t1[cg+0], 0.0f);
            float a1 = fmaxf(v.y * s1[cg+1] + t1[cg+1], 0.0f);
            float a2 = fmaxf(v.z * s1[cg+2] + t1[cg+2], 0.0f);
            float a3 = fmaxf(v.w * s1[cg+3] + t1[cg+3], 0.0f);
            uint32_t h01, l01, h23, l23;
            split2(a0, a1, h01, l01); split2(a2, a3, h23, l23);
            int bo = tid * ASTRIDE + q * 8;
            *(uint32_t*)(smem + A_AHI + bo)     = h01;
            *(uint32_t*)(smem + A_AHI + bo + 4) = h23;
            *(uint32_t*)(smem + A_ALO + bo)     = l01;
            *(uint32_t*)(smem + A_ALO + bo + 4) = l23;
        }
        build_B128(smem, A_BHI, A_BLO, w1 + (size_t)(ch * 64) * MID, MID, tid);
        __syncthreads();
        gemm_chunk32(sb, A_AHI, A_ALO, A_BHI, A_BLO, aoff, boff, acc);
    }

    // epilogue: bn2+relu, split, store h2 (4 row groups)
    const int r0 = m0 + wid * 32 + (lane >> 2);
    #pragma unroll
    for (int nt = 0; nt < 8; nt++) {
        int c0 = nt * 8 + (lane & 3) * 2;
        #pragma unroll
        for (int rr = 0; rr < 4; rr++) {
            int r = r0 + rr * 8;
            const float* a = acc[rr >> 1][nt] + (rr & 1) * 2;
            float v0 = fmaxf(a[0] * s2[c0]   + u2[c0],   0.0f);
            float v1 = fmaxf(a[1] * s2[c0+1] + u2[c0+1], 0.0f);
            uint32_t h, l; split2(v0, v1, h, l);
            *(uint32_t*)(g_h2hi + (size_t)r * MID + c0) = h;
            *(uint32_t*)(g_h2lo + (size_t)r * MID + c0) = l;
        }
    }
}

// ---------------------------------------------------------------------------
// Fused kBC (R9 structure): 128 threads, warp tile 32x64, 3 CTAs/SM.
// B tiles now cp.async'd from pre-split g_w2t/g_w3t (no build_B ALU/STS).
// ---------------------------------------------------------------------------
#define G_AHI 0
#define G_ALO 18432
#define G_B   36864   /* hi 36864, lo 46080 */
#define G_PAR 55296

__global__ void __launch_bounds__(128, 3)
kBC(const float* __restrict__ x,
    const float* __restrict__ g1, const float* __restrict__ be1,
    const float* __restrict__ mu1, const float* __restrict__ va1,
    const float* __restrict__ b2,
    const float* __restrict__ g3, const float* __restrict__ be3,
    const float* __restrict__ mu3, const float* __restrict__ va3,
    const float* __restrict__ b3,
    const int* __restrict__ nbr, const void* __restrict__ maskp,
    float* __restrict__ out)
{
    extern __shared__ char smem[];
    const uint32_t sb = smem_to_u32(smem);
    float* s3  = (float*)(smem + G_PAR);
    float* u3  = s3 + 64;
    float* s1a = u3 + 64;
    float* t1a = s1a + 256;
    float* b3a = t1a + 256;

    const int tid = threadIdx.x, lane = tid & 31, wid = tid >> 5;
    if (tid < 64) {
        float s = g3[tid] * rsqrtf(va3[tid] + EPS);
        s3[tid] = s;
        u3[tid] = b2[tid] * s + (be3[tid] - mu3[tid] * s);
    }
    #pragma unroll
    for (int c = tid; c < 256; c += 128) {
        float s = g1[c] * rsqrtf(va1[c] + EPS);
        s1a[c] = s; t1a[c] = be1[c] - mu1[c] * s; b3a[c] = b3[c];
    }

    const int m0 = blockIdx.x * 128;
    const int mode = g_mask_mode;
    const uint32_t aoff = a_off(wid * 32, lane), boff = b_off(lane);
    const size_t eb = (size_t)(m0 + tid) * KOFF;

    float acc[2][8][4] = {};
    int  nidx = nbr[eb];
    bool non  = mask_on(maskp, eb, mode);

    // ---------------- Phase 1: 9 gather chunks ----------------
    for (int k = 0; k < KOFF; k++) {
        __syncthreads();                 // gemm(k-1) done: A + B reusable
        {                                // gather(k): one h2 row per thread
            uint32_t sz = non ? 16u : 0u;
            const char* hp = (const char*)(g_h2hi + (size_t)nidx * MID);
            const char* lp = (const char*)(g_h2lo + (size_t)nidx * MID);
            uint32_t dh = sb + G_AHI + tid * ASTRIDE;
            uint32_t dl = sb + G_ALO + tid * ASTRIDE;
            #pragma unroll
            for (int q = 0; q < 8; q++) {
                CP_ASYNC16(dh + q * 16, hp + q * 16, sz);
                CP_ASYNC16(dl + q * 16, lp + q * 16, sz);
            }
            CP_COMMIT();
        }
        copy_tile128(sb + G_B, g_w2t + k * 1152, tid); CP_COMMIT();
        if (k < KOFF - 1) {
            nidx = nbr[eb + k + 1];
            non  = mask_on(maskp, eb + k + 1, mode);
        }
        CP_WAIT0();
        __syncthreads();
        gemm_chunk32(sb, G_AHI, G_ALO, G_B, G_B + 9216, aoff, boff, acc);
    }

    // ---------------- Transition: h4 = relu(bn3(acc)) -> A buffer ----------------
    __syncthreads();
    {
        const int rl = wid * 32 + (lane >> 2);
        #pragma unroll
        for (int nt = 0; nt < 8; nt++) {
            int c0 = nt * 8 + (lane & 3) * 2;
            #pragma unroll
            for (int rr = 0; rr < 4; rr++) {
                int r = rl + rr * 8;
                const float* a = acc[rr >> 1][nt] + (rr & 1) * 2;
                float v0 = fmaxf(a[0] * s3[c0]   + u3[c0],   0.0f);
                float v1 = fmaxf(a[1] * s3[c0+1] + u3[c0+1], 0.0f);
                uint32_t h, l; split2(v0, v1, h, l);
                int bo = r * ASTRIDE + c0 * 2;
                *(uint32_t*)(smem + G_AHI + bo) = h;
                *(uint32_t*)(smem + G_ALO + bo) = l;
            }
        }
    }

    // ---------------- Phase 2: 4 col slices of 64 ----------------
    const int rbase = m0 + wid * 32 + (lane >> 2);
    for (int s = 0; s < 4; s++) {
        __syncthreads();
        copy_tile128(sb + G_B, g_w3t + s * 1152, tid); CP_COMMIT();
        CP_WAIT0();
        __syncthreads();
        float acc2[2][8][4] = {};
        gemm_chunk32(sb, G_AHI, G_ALO, G_B, G_B + 9216, aoff, boff, acc2);

        #pragma unroll
        for (int nt = 0; nt < 8; nt++) {
            int lc = nt * 8 + (lane & 3) * 2;
            int c = s * 64 + lc;
            #pragma unroll
            for (int rr = 0; rr < 4; rr++) {
                int r = rbase + rr * 8;
                const float* a = acc2[rr >> 1][nt] + (rr & 1) * 2;
                float2 xv = *reinterpret_cast<const float2*>(x + (size_t)r * CIN + c);
                float o0 = a[0] + b3a[c]   + fmaxf(xv.x * s1a[c]   + t1a[c],   0.0f);
                float o1 = a[1] + b3a[c+1] + fmaxf(xv.y * s1a[c+1] + t1a[c+1], 0.0f);
                *reinterpret_cast<float2*>(out + (size_t)r * CIN + c) = make_float2(o0, o1);
            }
        }
    }
}

// ---------------------------------------------------------------------------
extern "C" void kernel_launch(void* const* d_in, const int* in_sizes, int n_in,
                              void* d_out, int out_size)
{
    const float* x     = (const float*)d_in[0];
    const float* bn1_g = (const float*)d_in[1];
    const float* bn1_b = (const float*)d_in[2];
    const float* bn1_m = (const float*)d_in[3];
    const float* bn1_v = (const float*)d_in[4];
    const float* w1    = (const float*)d_in[5];
    const float* b1    = (const float*)d_in[6];
    const float* bn2_g = (const float*)d_in[7];
    const float* bn2_b = (const float*)d_in[8];
    const float* bn2_m = (const float*)d_in[9];
    const float* bn2_v = (const float*)d_in[10];
    const float* w2    = (const float*)d_in[11];
    const float* b2    = (const float*)d_in[12];
    const float* bn3_g = (const float*)d_in[13];
    const float* bn3_b = (const float*)d_in[14];
    const float* bn3_m = (const float*)d_in[15];
    const float* bn3_v = (const float*)d_in[16];
    const float* w3    = (const float*)d_in[17];
    const float* b3    = (const float*)d_in[18];
    const int*   nbr   = (const int*)d_in[19];
    const void*  msk   = (const void*)d_in[20];
    float* out = (float*)d_out;

    const int SMA  = A_PAR + (256 + 256 + 64 + 64) * 4;
    const int SMBC = G_PAR + (64 + 64 + 256 + 256 + 256) * 4;
    cudaFuncSetAttribute(kA,  cudaFuncAttributeMaxDynamicSharedMemorySize, SMA);
    cudaFuncSetAttribute(kBC, cudaFuncAttributeMaxDynamicSharedMemorySize, SMBC);

    kA<<<NROWS / 128 + 14, 128, SMA>>>(x, bn1_g, bn1_b, bn1_m, bn1_v, w1, b1,
                                       bn2_g, bn2_b, bn2_m, bn2_v, w2, w3,
                                       (const unsigned char*)msk);
    kBC<<<NROWS / 128, 128, SMBC>>>(x, bn1_g, bn1_b, bn1_m, bn1_v,
                                    b2, bn3_g, bn3_b, bn3_m, bn3_v,
                                    b3, nbr, msk, out);
    (void)in_sizes; (void)n_in; (void)out_size;
}